// round 13
// baseline (speedup 1.0000x reference)
#include <cuda_runtime.h>
#include <cuda_fp16.h>
#include <math.h>
#include <stdint.h>

// ---------------- problem constants ----------------
#define Bsz   32
#define Cch   384
#define Hh    56
#define Wwid  56
#define WS    7
#define SSH   3
#define NHd   12
#define Ntok  49
#define HDim  32
#define HIDd  1536
#define NWTOT 2048
#define Mrows (NWTOT*Ntok)         // 100352
#define SCALE 0.17677669529663687f

// ---------------- scratch ----------------
constexpr size_t OFF_XRAW = 0;                                  // [M,384] f32
constexpr size_t OFF_Y    = OFF_XRAW + (size_t)Mrows*Cch;       // [M,384] f32
constexpr size_t OFF_FIN  = OFF_Y    + (size_t)Mrows*Cch;       // [M,384] f32
constexpr size_t SCRATCH_F = OFF_FIN + (size_t)Mrows*Cch;

constexpr size_t HOFF_XLN  = 0;
constexpr size_t HOFF_QKV  = HOFF_XLN  + (size_t)Mrows*Cch;
constexpr size_t HOFF_ATT  = HOFF_QKV  + (size_t)Mrows*(3*Cch);
constexpr size_t HOFF_YLN  = HOFF_ATT  + (size_t)Mrows*Cch;
constexpr size_t HOFF_H    = HOFF_YLN  + (size_t)Mrows*Cch;
constexpr size_t HOFF_WQKV = HOFF_H    + (size_t)Mrows*HIDd;
constexpr size_t HOFF_WPRJ = HOFF_WQKV + (size_t)1152*384;
constexpr size_t HOFF_WFC1 = HOFF_WPRJ + (size_t)384*384;
constexpr size_t HOFF_WFC2 = HOFF_WFC1 + (size_t)1536*384;
constexpr size_t SCRATCH_H = HOFF_WFC2 + (size_t)384*1536;

__device__ __align__(16) float  g_f[SCRATCH_F];
__device__ __align__(16) __half g_h[SCRATCH_H];

// ---------------- helpers ----------------
__device__ __forceinline__ int region(int p) {
    return p < (Hh - WS) ? 0 : (p < (Hh - SSH) ? 1 : 2);
}
__device__ __forceinline__ float gelu_exact(float v) {
    return 0.5f * v * (1.0f + erff(v * 0.70710678118654752f));
}
__device__ __forceinline__ void mma_f16(float c[4], const uint32_t a[4], const uint32_t b[2]) {
    asm volatile(
        "mma.sync.aligned.m16n8k16.row.col.f32.f16.f16.f32 "
        "{%0,%1,%2,%3}, {%4,%5,%6,%7}, {%8,%9}, {%0,%1,%2,%3};\n"
        : "+f"(c[0]), "+f"(c[1]), "+f"(c[2]), "+f"(c[3])
        : "r"(a[0]), "r"(a[1]), "r"(a[2]), "r"(a[3]), "r"(b[0]), "r"(b[1]));
}
__device__ __forceinline__ void cpa16(uint32_t dst, const void* src) {
    asm volatile("cp.async.cg.shared.global [%0], [%1], 16;" :: "r"(dst), "l"(src));
}
__device__ __forceinline__ void cpa_commit() {
    asm volatile("cp.async.commit_group;" ::: "memory");
}
template <int N>
__device__ __forceinline__ void cpa_wait() {
    asm volatile("cp.async.wait_group %0;" :: "n"(N) : "memory");
}

// ---------------- fused transpose-in + LN1 ----------------
#define XS_STRIDE 57
constexpr int SMEM_TIN_BYTES = 384 * XS_STRIDE * 4;   // 87552

__global__ void __launch_bounds__(256) tinln_kernel(
    const float* __restrict__ x, const float* __restrict__ gam,
    const float* __restrict__ bet)
{
    extern __shared__ float xs[];
    int hh = blockIdx.x, b = blockIdx.y;
    int tid = threadIdx.x;
    int h0 = hh + SSH; if (h0 >= Hh) h0 -= Hh;

    const float* src = x + ((size_t)b*Cch)*(Hh*Wwid) + h0*Wwid;
    for (int e = tid; e < 384*56; e += 256) {
        int c = e / 56, ws = e - c*56;
        xs[c*XS_STRIDE + ws] = src[(size_t)c*(Hh*Wwid) + ws];
    }
    __syncthreads();

    int warp = tid >> 5, lane = tid & 31;
    int wh = hh / WS, r = hh % WS;

    float gm[12], bt[12];
    #pragma unroll
    for (int j = 0; j < 12; j++) { gm[j] = gam[lane + 32*j]; bt[j] = bet[lane + 32*j]; }

    for (int ts = warp*7; ts < warp*7 + 7; ts++) {
        int wsrc = ts + SSH; if (wsrc >= Wwid) wsrc -= Wwid;
        float v[12];
        float s = 0.f, s2 = 0.f;
        #pragma unroll
        for (int j = 0; j < 12; j++) {
            float t = xs[(lane + 32*j)*XS_STRIDE + wsrc];
            v[j] = t; s += t; s2 += t*t;
        }
        #pragma unroll
        for (int o = 16; o; o >>= 1) {
            s  += __shfl_xor_sync(0xffffffffu, s,  o);
            s2 += __shfl_xor_sync(0xffffffffu, s2, o);
        }
        float mean = s * (1.0f/Cch);
        float var  = s2 * (1.0f/Cch) - mean*mean;
        float inv  = rsqrtf(var + 1e-5f);

        int ww = ts / WS, cc = ts % WS;
        int m = (((b*8 + wh)*8 + ww)*Ntok) + r*WS + cc;
        float*  xr = g_f + OFF_XRAW + (size_t)m*Cch;
        __half* xl = g_h + HOFF_XLN + (size_t)m*Cch;
        #pragma unroll
        for (int j = 0; j < 12; j++) {
            int d = lane + 32*j;
            xr[d] = v[j];
            xl[d] = __float2half_rn((v[j]-mean)*inv*gm[j] + bt[j]);
        }
    }
}

// ---------------- transpose-out ----------------
__global__ void __launch_bounds__(256) tout_kernel(float* __restrict__ out) {
    int ct = blockIdx.x, h0 = blockIdx.y, b = blockIdx.z;
    __shared__ float tile[32][57];
    int hh = h0 - SSH; if (hh < 0) hh += Hh;
    int wh = hh / WS, r = hh % WS;
    for (int idx = threadIdx.x; idx < 56*32; idx += 256) {
        int t = idx >> 5, i = idx & 31;
        int ww = t / WS, c = t % WS;
        int m = (((b*8 + wh)*8 + ww)*Ntok) + r*WS + c;
        int w0 = t + SSH; if (w0 >= Wwid) w0 -= Wwid;
        tile[i][w0] = g_f[OFF_FIN + (size_t)m*Cch + ct*32 + i];
    }
    __syncthreads();
    for (int idx = threadIdx.x; idx < 32*56; idx += 256) {
        int i = idx / 56, w0 = idx - i*56;
        out[((size_t)(b*Cch + ct*32 + i))*(Hh*Wwid) + h0*Wwid + w0] = tile[i][w0];
    }
}

// ---------------- weight transpose [K][N] f32 -> [N][K] half ----------------
__global__ void __launch_bounds__(256) wtrans_kernel(const float* __restrict__ W,
                                                     int K, int N, size_t outoff) {
    __shared__ float t[32][33];
    int n0 = blockIdx.x*32, k0 = blockIdx.y*32;
    int tx = threadIdx.x & 31, ty = threadIdx.x >> 5;
    __half* out = g_h + outoff;
    for (int i = ty; i < 32; i += 8)
        t[i][tx] = W[(size_t)(k0+i)*N + n0+tx];
    __syncthreads();
    for (int i = ty; i < 32; i += 8)
        out[(size_t)(n0+i)*K + k0+tx] = __float2half_rn(t[tx][i]);
}

// ---------------- layernorm2: fp32 in -> fp16 out ----------------
__global__ void __launch_bounds__(128) ln_kernel(size_t Xoff, const float* __restrict__ gam,
                                                 const float* __restrict__ bet, size_t Yoff) {
    int row = blockIdx.x;
    const float* x = g_f + Xoff + (size_t)row*Cch;
    __half*      y = g_h + Yoff + (size_t)row*Cch;
    int c = threadIdx.x;
    float v0 = x[c], v1 = x[c+128], v2 = x[c+256];
    float s = v0+v1+v2, s2 = v0*v0 + v1*v1 + v2*v2;
    #pragma unroll
    for (int o = 16; o; o >>= 1) {
        s  += __shfl_xor_sync(0xffffffffu, s,  o);
        s2 += __shfl_xor_sync(0xffffffffu, s2, o);
    }
    __shared__ float rs[4], rs2[4];
    int wid = c >> 5;
    if ((c & 31) == 0) { rs[wid] = s; rs2[wid] = s2; }
    __syncthreads();
    s  = rs[0]+rs[1]+rs[2]+rs[3];
    s2 = rs2[0]+rs2[1]+rs2[2]+rs2[3];
    float mean = s * (1.0f/Cch);
    float var  = s2 * (1.0f/Cch) - mean*mean;
    float inv  = rsqrtf(var + 1e-5f);
    y[c]     = __float2half_rn((v0-mean)*inv*gam[c]     + bet[c]);
    y[c+128] = __float2half_rn((v1-mean)*inv*gam[c+128] + bet[c+128]);
    y[c+256] = __float2half_rn((v2-mean)*inv*gam[c+256] + bet[c+256]);
}

// ---------------- fp16 GEMM: BK=16, 6 stages, 2 k-tiles per barrier ----------
#define EPI_BIAS_H 0
#define EPI_RES_F  1
#define EPI_GELU_H 2

#define HT_STG (128*16)
#define STAGES 6
constexpr int SMEM_HGEMM_BYTES = STAGES * 2 * HT_STG * 2;   // 49152

__global__ void __launch_bounds__(256, 2) hgemm_kernel(
    size_t Aoff, size_t Boff, const float* __restrict__ bias,
    long long resoff, size_t Coff, int N, int K, int epi)
{
    extern __shared__ __half smh[];
    __half* As = smh;
    __half* Bs = smh + STAGES*HT_STG;
    uint32_t as_sm = (uint32_t)__cvta_generic_to_shared(As);
    uint32_t bs_sm = (uint32_t)__cvta_generic_to_shared(Bs);

    int tid = threadIdx.x;
    int warp = tid >> 5, lane = tid & 31;
    int wrow = warp >> 2, wcol = warp & 3;
    int g = lane >> 2, qc = lane & 3;
    int brow = blockIdx.y, bcol = blockIdx.x;

    const __half* Ablk = g_h + Aoff + (size_t)brow*128*K;
    const __half* Bblk = g_h + Boff + (size_t)bcol*128*K;

    int lrow = tid >> 1;
    int lch  = (tid & 1) * 8;

    auto load_tile = [&](int s, int kt) {
        const __half* Ap = Ablk + (size_t)lrow*K + kt*16 + lch;
        const __half* Bp = Bblk + (size_t)lrow*K + kt*16 + lch;
        uint32_t off = (uint32_t)(s*HT_STG + lrow*16 + lch) * 2;
        cpa16(as_sm + off, Ap);
        cpa16(bs_sm + off, Bp);
    };

    float acc[4][4][4];
    #pragma unroll
    for (int i = 0; i < 4; i++)
        #pragma unroll
        for (int j = 0; j < 4; j++)
            #pragma unroll
            for (int r = 0; r < 4; r++) acc[i][j][r] = 0.f;

    auto compute_stage = [&](int stage) {
        const __half* Asb = As + stage*HT_STG;
        const __half* Bsb = Bs + stage*HT_STG;
        uint32_t af[4][4];
        #pragma unroll
        for (int i = 0; i < 4; i++) {
            int r = wrow*64 + i*16 + g;
            uint2 lo = *(const uint2*)(Asb + r*16     + 4*qc);
            uint2 hi = *(const uint2*)(Asb + (r+8)*16 + 4*qc);
            af[i][0] = lo.x; af[i][1] = hi.x; af[i][2] = lo.y; af[i][3] = hi.y;
        }
        uint32_t bf[4][2];
        #pragma unroll
        for (int j = 0; j < 4; j++) {
            int c = wcol*32 + j*8 + g;
            uint2 bb = *(const uint2*)(Bsb + c*16 + 4*qc);
            bf[j][0] = bb.x; bf[j][1] = bb.y;
        }
        #pragma unroll
        for (int i = 0; i < 4; i++)
            #pragma unroll
            for (int j = 0; j < 4; j++)
                mma_f16(acc[i][j], af[i], bf[j]);
    };

    int nk = K >> 4;           // even (24 or 96) for all our GEMMs
    // prologue: tiles 0..3 in two groups
    load_tile(0, 0); load_tile(1, 1); cpa_commit();
    load_tile(2, 2); load_tile(3, 3); cpa_commit();
    cpa_wait<1>();             // tiles 0,1 resident
    __syncthreads();

    int s0 = 0;                // stage of tile kt
    for (int kt = 0; kt < nk; kt += 2) {
        if (kt + 4 < nk) {
            int sa = s0 + 4 >= STAGES ? s0 + 4 - STAGES : s0 + 4;
            int sb = sa + 1 == STAGES ? 0 : sa + 1;
            load_tile(sa, kt + 4);
            load_tile(sb, kt + 5);
        }
        cpa_commit();          // one group per iteration (possibly empty)

        compute_stage(s0);
        int s1 = s0 + 1 == STAGES ? 0 : s0 + 1;
        compute_stage(s1);

        cpa_wait<1>();         // tiles kt+2, kt+3 resident
        __syncthreads();
        s0 = s0 + 2 >= STAGES ? s0 + 2 - STAGES : s0 + 2;
    }

    const float* res = (resoff >= 0) ? (g_f + (size_t)resoff) : nullptr;
    #pragma unroll
    for (int i = 0; i < 4; i++) {
        int r0 = brow*128 + wrow*64 + i*16 + g;
        #pragma unroll
        for (int j = 0; j < 4; j++) {
            int cb = bcol*128 + wcol*32 + j*8 + qc*2;
            float bx = bias[cb], by = bias[cb+1];
            #pragma unroll
            for (int half_ = 0; half_ < 2; half_++) {
                int row = r0 + half_*8;
                float vx = acc[i][j][half_*2]   + bx;
                float vy = acc[i][j][half_*2+1] + by;
                if (epi == EPI_RES_F) {
                    float2 rr = *(const float2*)(res + (size_t)row*N + cb);
                    vx += rr.x; vy += rr.y;
                    float2 o = {vx, vy};
                    *(float2*)(g_f + Coff + (size_t)row*N + cb) = o;
                } else {
                    if (epi == EPI_GELU_H) { vx = gelu_exact(vx); vy = gelu_exact(vy); }
                    *(__half2*)(g_h + Coff + (size_t)row*N + cb) =
                        __floats2half2_rn(vx, vy);
                }
            }
        }
    }
}

// ---------------- tensor-core attention, register-resident P -----------------
__global__ void __launch_bounds__(128) attn_kernel(const float* __restrict__ rpb) {
    int blk = blockIdx.x;
    int h = blk % NHd;
    int w = blk / NHd;
    int ww = w & 7, wh = (w >> 3) & 7;
    int m0 = w * Ntok;

    __shared__ __half qh[64][40];
    __shared__ __half kh[56][40];
    __shared__ __half vT[32][72];
    __shared__ float  rpbh[169];
    __shared__ int    rid[Ntok];

    int tid = threadIdx.x;
    int warp = tid >> 5, lane = tid & 31;
    int g = lane >> 2, qc = lane & 3;

    for (int e = tid; e < 480; e += 128)
        vT[e / 15][49 + e % 15] = __float2half_rn(0.f);

    const __half* qkv = g_h + HOFF_QKV;
    if (tid < 98) {
        int i = tid >> 1, p = tid & 1;
        const __half* base = qkv + (size_t)(m0 + i)*(3*Cch) + h*HDim + p*16;
        *(uint4*)&qh[i][p*16]     = *(const uint4*)(base);
        *(uint4*)&qh[i][p*16 + 8] = *(const uint4*)(base + 8);
        *(uint4*)&kh[i][p*16]     = *(const uint4*)(base + Cch);
        *(uint4*)&kh[i][p*16 + 8] = *(const uint4*)(base + Cch + 8);
        const __half* vbase = base + 2*Cch;
        #pragma unroll
        for (int d = 0; d < 16; d++)
            vT[p*16 + d][i] = vbase[d];
    }
    for (int e = tid; e < 169; e += 128) rpbh[e] = rpb[e*NHd + h];
    if (tid < Ntok) {
        int r = tid / WS, c = tid % WS;
        rid[tid] = region(wh*WS + r)*3 + region(ww*WS + c);
    }
    __syncthreads();

    int r = warp*16 + g;
    int rlo = r, rhi = r + 8;
    bool lo_ok = rlo < Ntok, hi_ok = rhi < Ntok;
    int rid_lo = lo_ok ? rid[rlo] : 0;
    int rid_hi = hi_ok ? rid[rhi] : 0;
    int ri_lo = rlo / WS, ci_lo = rlo % WS;
    int ri_hi = rhi / WS, ci_hi = rhi % WS;

    float s[7][4];
    {
        uint32_t af[2][4];
        #pragma unroll
        for (int kc = 0; kc < 2; kc++) {
            af[kc][0] = *(const uint32_t*)&qh[rlo][kc*16 + 2*qc];
            af[kc][1] = *(const uint32_t*)&qh[rhi][kc*16 + 2*qc];
            af[kc][2] = *(const uint32_t*)&qh[rlo][kc*16 + 2*qc + 8];
            af[kc][3] = *(const uint32_t*)&qh[rhi][kc*16 + 2*qc + 8];
        }
        #pragma unroll
        for (int jt = 0; jt < 7; jt++) {
            float c4[4] = {0.f, 0.f, 0.f, 0.f};
            int col = jt*8 + g;
            uint32_t bf0[2], bf1[2];
            bf0[0] = *(const uint32_t*)&kh[col][2*qc];
            bf0[1] = *(const uint32_t*)&kh[col][2*qc + 8];
            bf1[0] = *(const uint32_t*)&kh[col][16 + 2*qc];
            bf1[1] = *(const uint32_t*)&kh[col][16 + 2*qc + 8];
            mma_f16(c4, af[0], bf0);
            mma_f16(c4, af[1], bf1);
            int c0 = jt*8 + 2*qc;
            #pragma unroll
            for (int u = 0; u < 4; u++) {
                int row_ok = (u & 2) ? hi_ok : lo_ok;
                int ccol = c0 + (u & 1);
                if (row_ok && ccol < Ntok) {
                    int ri = (u & 2) ? ri_hi : ri_lo;
                    int ci = (u & 2) ? ci_hi : ci_lo;
                    int rd = (u & 2) ? rid_hi : rid_lo;
                    int rj = ccol / WS, cj = ccol % WS;
                    float v = c4[u]*SCALE + rpbh[(ri - rj + 6)*13 + (ci - cj + 6)];
                    if (rd != rid[ccol]) v -= 100.f;
                    s[jt][u] = v;
                } else {
                    s[jt][u] = -1e30f;
                }
            }
        }
    }

    {
        float m_lo = -1e30f, m_hi = -1e30f;
        #pragma unroll
        for (int jt = 0; jt < 7; jt++) {
            m_lo = fmaxf(m_lo, fmaxf(s[jt][0], s[jt][1]));
            m_hi = fmaxf(m_hi, fmaxf(s[jt][2], s[jt][3]));
        }
        m_lo = fmaxf(m_lo, __shfl_xor_sync(0xffffffffu, m_lo, 1));
        m_lo = fmaxf(m_lo, __shfl_xor_sync(0xffffffffu, m_lo, 2));
        m_hi = fmaxf(m_hi, __shfl_xor_sync(0xffffffffu, m_hi, 1));
        m_hi = fmaxf(m_hi, __shfl_xor_sync(0xffffffffu, m_hi, 2));
        float sum_lo = 0.f, sum_hi = 0.f;
        #pragma unroll
        for (int jt = 0; jt < 7; jt++) {
            s[jt][0] = __expf(s[jt][0] - m_lo); sum_lo += s[jt][0];
            s[jt][1] = __expf(s[jt][1] - m_lo); sum_lo += s[jt][1];
            s[jt][2] = __expf(s[jt][2] - m_hi); sum_hi += s[jt][2];
            s[jt][3] = __expf(s[jt][3] - m_hi); sum_hi += s[jt][3];
        }
        sum_lo += __shfl_xor_sync(0xffffffffu, sum_lo, 1);
        sum_lo += __shfl_xor_sync(0xffffffffu, sum_lo, 2);
        sum_hi += __shfl_xor_sync(0xffffffffu, sum_hi, 1);
        sum_hi += __shfl_xor_sync(0xffffffffu, sum_hi, 2);
        float inv_lo = 1.0f / sum_lo, inv_hi = 1.0f / sum_hi;
        #pragma unroll
        for (int jt = 0; jt < 7; jt++) {
            s[jt][0] *= inv_lo; s[jt][1] *= inv_lo;
            s[jt][2] *= inv_hi; s[jt][3] *= inv_hi;
        }
    }

    uint32_t paf[4][4];
    #pragma unroll
    for (int kc = 0; kc < 3; kc++) {
        __half2 a0 = __floats2half2_rn(s[2*kc][0],   s[2*kc][1]);
        __half2 a1 = __floats2half2_rn(s[2*kc][2],   s[2*kc][3]);
        __half2 a2 = __floats2half2_rn(s[2*kc+1][0], s[2*kc+1][1]);
        __half2 a3 = __floats2half2_rn(s[2*kc+1][2], s[2*kc+1][3]);
        paf[kc][0] = *(uint32_t*)&a0; paf[kc][1] = *(uint32_t*)&a1;
        paf[kc][2] = *(uint32_t*)&a2; paf[kc][3] = *(uint32_t*)&a3;
    }
    {
        __half2 a0 = __floats2half2_rn(s[6][0], s[6][1]);
        __half2 a1 = __floats2half2_rn(s[6][2], s[6][3]);
        paf[3][0] = *(uint32_t*)&a0; paf[3][1] = *(uint32_t*)&a1;
        paf[3][2] = 0u; paf[3][3] = 0u;
    }

    __half* att = g_h + HOFF_ATT;
    #pragma unroll
    for (int ct = 0; ct < 4; ct++) {
        float c4[4] = {0.f, 0.f, 0.f, 0.f};
        int dcol = ct*8 + g;
        #pragma unroll
        for (int kc = 0; kc < 4; kc++) {
            uint32_t bf[2];
            bf[0] = *(const uint32_t*)&vT[dcol][kc*16 + 2*qc];
            bf[1] = *(const uint32_t*)&vT[dcol][kc*16 + 2*qc + 8];
            mma_f16(c4, paf[kc], bf);
        }
        int c0 = ct*8 + 2*qc;
        if (lo_ok)
            *(__half2*)(att + (size_t)(m0 + rlo)*Cch + h*HDim + c0) =
                __floats2half2_rn(c4[0], c4[1]);
        if (hi_ok)
            *(__half2*)(att + (size_t)(m0 + rhi)*Cch + h*HDim + c0) =
                __floats2half2_rn(c4[2], c4[3]);
    }
}

// ---------------- launch ----------------
extern "C" void kernel_launch(void* const* d_in, const int* in_sizes, int n_in,
                              void* d_out, int out_size) {
    const float* x      = (const float*)d_in[0];
    const float* qkv_w  = (const float*)d_in[1];
    const float* qkv_b  = (const float*)d_in[2];
    const float* proj_w = (const float*)d_in[3];
    const float* proj_b = (const float*)d_in[4];
    const float* rpb    = (const float*)d_in[5];
    const float* n1w    = (const float*)d_in[6];
    const float* n1b    = (const float*)d_in[7];
    const float* n2w    = (const float*)d_in[8];
    const float* n2b    = (const float*)d_in[9];
    const float* fc1w   = (const float*)d_in[10];
    const float* fc1b   = (const float*)d_in[11];
    const float* fc2w   = (const float*)d_in[12];
    const float* fc2b   = (const float*)d_in[13];
    float* out = (float*)d_out;

    cudaFuncSetAttribute(hgemm_kernel, cudaFuncAttributeMaxDynamicSharedMemorySize,
                         SMEM_HGEMM_BYTES);
    cudaFuncSetAttribute(tinln_kernel, cudaFuncAttributeMaxDynamicSharedMemorySize,
                         SMEM_TIN_BYTES);

    wtrans_kernel<<<dim3(1152/32, 384/32), 256>>>(qkv_w, Cch, 1152, HOFF_WQKV);
    wtrans_kernel<<<dim3(384/32,  384/32), 256>>>(proj_w, Cch, 384,  HOFF_WPRJ);
    wtrans_kernel<<<dim3(1536/32, 384/32), 256>>>(fc1w,  Cch, 1536, HOFF_WFC1);
    wtrans_kernel<<<dim3(384/32, 1536/32), 256>>>(fc2w,  HIDd, 384, HOFF_WFC2);

    tinln_kernel<<<dim3(56, 32), 256, SMEM_TIN_BYTES>>>(x, n1w, n1b);
    hgemm_kernel<<<dim3(1152/128, Mrows/128), 256, SMEM_HGEMM_BYTES>>>(
        HOFF_XLN, HOFF_WQKV, qkv_b, -1, HOFF_QKV, 1152, Cch, EPI_BIAS_H);
    attn_kernel<<<NWTOT * NHd, 128>>>(rpb);
    hgemm_kernel<<<dim3(384/128, Mrows/128), 256, SMEM_HGEMM_BYTES>>>(
        HOFF_ATT, HOFF_WPRJ, proj_b, (long long)OFF_XRAW, OFF_Y, Cch, Cch, EPI_RES_F);
    ln_kernel<<<Mrows, 128>>>(OFF_Y, n2w, n2b, HOFF_YLN);
    hgemm_kernel<<<dim3(1536/128, Mrows/128), 256, SMEM_HGEMM_BYTES>>>(
        HOFF_YLN, HOFF_WFC1, fc1b, -1, HOFF_H, HIDd, Cch, EPI_GELU_H);
    hgemm_kernel<<<dim3(384/128, Mrows/128), 256, SMEM_HGEMM_BYTES>>>(
        HOFF_H, HOFF_WFC2, fc2b, (long long)OFF_Y, OFF_FIN, Cch, HIDd, EPI_RES_F);
    tout_kernel<<<dim3(12, 56, 32), 256>>>(out);
}

// round 14
// speedup vs baseline: 1.0546x; 1.0546x over previous
#include <cuda_runtime.h>
#include <cuda_fp16.h>
#include <math.h>
#include <stdint.h>

// ---------------- problem constants ----------------
#define Bsz   32
#define Cch   384
#define Hh    56
#define Wwid  56
#define WS    7
#define SSH   3
#define NHd   12
#define Ntok  49
#define HDim  32
#define HIDd  1536
#define NWTOT 2048
#define Mrows (NWTOT*Ntok)         // 100352
#define SCALE 0.17677669529663687f

// ---------------- scratch ----------------
constexpr size_t OFF_XRAW = 0;                                  // [M,384] f32
constexpr size_t OFF_Y    = OFF_XRAW + (size_t)Mrows*Cch;       // [M,384] f32
constexpr size_t OFF_FIN  = OFF_Y    + (size_t)Mrows*Cch;       // [M,384] f32
constexpr size_t SCRATCH_F = OFF_FIN + (size_t)Mrows*Cch;

constexpr size_t HOFF_XLN  = 0;
constexpr size_t HOFF_QKV  = HOFF_XLN  + (size_t)Mrows*Cch;
constexpr size_t HOFF_ATT  = HOFF_QKV  + (size_t)Mrows*(3*Cch);
constexpr size_t HOFF_YLN  = HOFF_ATT  + (size_t)Mrows*Cch;
constexpr size_t HOFF_H    = HOFF_YLN  + (size_t)Mrows*Cch;
constexpr size_t HOFF_WQKV = HOFF_H    + (size_t)Mrows*HIDd;
constexpr size_t HOFF_WPRJ = HOFF_WQKV + (size_t)1152*384;
constexpr size_t HOFF_WFC1 = HOFF_WPRJ + (size_t)384*384;
constexpr size_t HOFF_WFC2 = HOFF_WFC1 + (size_t)1536*384;
constexpr size_t SCRATCH_H = HOFF_WFC2 + (size_t)384*1536;

__device__ __align__(16) float  g_f[SCRATCH_F];
__device__ __align__(16) __half g_h[SCRATCH_H];

// ---------------- helpers ----------------
__device__ __forceinline__ int region(int p) {
    return p < (Hh - WS) ? 0 : (p < (Hh - SSH) ? 1 : 2);
}
__device__ __forceinline__ float gelu_exact(float v) {
    return 0.5f * v * (1.0f + erff(v * 0.70710678118654752f));
}
__device__ __forceinline__ void mma_f16(float c[4], const uint32_t a[4], const uint32_t b[2]) {
    asm volatile(
        "mma.sync.aligned.m16n8k16.row.col.f32.f16.f16.f32 "
        "{%0,%1,%2,%3}, {%4,%5,%6,%7}, {%8,%9}, {%0,%1,%2,%3};\n"
        : "+f"(c[0]), "+f"(c[1]), "+f"(c[2]), "+f"(c[3])
        : "r"(a[0]), "r"(a[1]), "r"(a[2]), "r"(a[3]), "r"(b[0]), "r"(b[1]));
}
__device__ __forceinline__ void cpa16(uint32_t dst, const void* src) {
    asm volatile("cp.async.cg.shared.global [%0], [%1], 16;" :: "r"(dst), "l"(src));
}
__device__ __forceinline__ void cpa_commit() {
    asm volatile("cp.async.commit_group;" ::: "memory");
}
template <int N>
__device__ __forceinline__ void cpa_wait() {
    asm volatile("cp.async.wait_group %0;" :: "n"(N) : "memory");
}

// ---------------- fused transpose-in + LN1 ----------------
#define XS_STRIDE 57
constexpr int SMEM_TIN_BYTES = 384 * XS_STRIDE * 4;   // 87552

__global__ void __launch_bounds__(256) tinln_kernel(
    const float* __restrict__ x, const float* __restrict__ gam,
    const float* __restrict__ bet)
{
    extern __shared__ float xs[];
    int hh = blockIdx.x, b = blockIdx.y;
    int tid = threadIdx.x;
    int h0 = hh + SSH; if (h0 >= Hh) h0 -= Hh;

    const float* src = x + ((size_t)b*Cch)*(Hh*Wwid) + h0*Wwid;
    for (int e = tid; e < 384*56; e += 256) {
        int c = e / 56, ws = e - c*56;
        xs[c*XS_STRIDE + ws] = src[(size_t)c*(Hh*Wwid) + ws];
    }
    __syncthreads();

    int warp = tid >> 5, lane = tid & 31;
    int wh = hh / WS, r = hh % WS;

    float gm[12], bt[12];
    #pragma unroll
    for (int j = 0; j < 12; j++) { gm[j] = gam[lane + 32*j]; bt[j] = bet[lane + 32*j]; }

    for (int ts = warp*7; ts < warp*7 + 7; ts++) {
        int wsrc = ts + SSH; if (wsrc >= Wwid) wsrc -= Wwid;
        float v[12];
        float s = 0.f, s2 = 0.f;
        #pragma unroll
        for (int j = 0; j < 12; j++) {
            float t = xs[(lane + 32*j)*XS_STRIDE + wsrc];
            v[j] = t; s += t; s2 += t*t;
        }
        #pragma unroll
        for (int o = 16; o; o >>= 1) {
            s  += __shfl_xor_sync(0xffffffffu, s,  o);
            s2 += __shfl_xor_sync(0xffffffffu, s2, o);
        }
        float mean = s * (1.0f/Cch);
        float var  = s2 * (1.0f/Cch) - mean*mean;
        float inv  = rsqrtf(var + 1e-5f);

        int ww = ts / WS, cc = ts % WS;
        int m = (((b*8 + wh)*8 + ww)*Ntok) + r*WS + cc;
        float*  xr = g_f + OFF_XRAW + (size_t)m*Cch;
        __half* xl = g_h + HOFF_XLN + (size_t)m*Cch;
        #pragma unroll
        for (int j = 0; j < 12; j++) {
            int d = lane + 32*j;
            xr[d] = v[j];
            xl[d] = __float2half_rn((v[j]-mean)*inv*gm[j] + bt[j]);
        }
    }
}

// ---------------- transpose-out ----------------
__global__ void __launch_bounds__(256) tout_kernel(float* __restrict__ out) {
    int ct = blockIdx.x, h0 = blockIdx.y, b = blockIdx.z;
    __shared__ float tile[32][57];
    int hh = h0 - SSH; if (hh < 0) hh += Hh;
    int wh = hh / WS, r = hh % WS;
    for (int idx = threadIdx.x; idx < 56*32; idx += 256) {
        int t = idx >> 5, i = idx & 31;
        int ww = t / WS, c = t % WS;
        int m = (((b*8 + wh)*8 + ww)*Ntok) + r*WS + c;
        int w0 = t + SSH; if (w0 >= Wwid) w0 -= Wwid;
        tile[i][w0] = g_f[OFF_FIN + (size_t)m*Cch + ct*32 + i];
    }
    __syncthreads();
    for (int idx = threadIdx.x; idx < 32*56; idx += 256) {
        int i = idx / 56, w0 = idx - i*56;
        out[((size_t)(b*Cch + ct*32 + i))*(Hh*Wwid) + h0*Wwid + w0] = tile[i][w0];
    }
}

// ---------------- batched weight transpose: all 4 weights, one launch --------
// blocks: qkv 36x12=432 | proj 12x12=144 | fc1 48x12=576 | fc2 12x48=576
__global__ void __launch_bounds__(256) wtrans_all_kernel(
    const float* __restrict__ Wq, const float* __restrict__ Wp,
    const float* __restrict__ W1, const float* __restrict__ W2)
{
    __shared__ float t[32][33];
    int bidx = blockIdx.x;
    const float* W; int K, N, nb_n; size_t outoff;
    if (bidx < 432)      { W = Wq; K = Cch;  N = 1152; nb_n = 36; outoff = HOFF_WQKV; }
    else if (bidx < 576) { W = Wp; K = Cch;  N = 384;  nb_n = 12; outoff = HOFF_WPRJ; bidx -= 432; }
    else if (bidx < 1152){ W = W1; K = Cch;  N = 1536; nb_n = 48; outoff = HOFF_WFC1; bidx -= 576; }
    else                 { W = W2; K = HIDd; N = 384;  nb_n = 12; outoff = HOFF_WFC2; bidx -= 1152; }
    int n0 = (bidx % nb_n) * 32, k0 = (bidx / nb_n) * 32;

    int tx = threadIdx.x & 31, ty = threadIdx.x >> 5;
    __half* outp = g_h + outoff;
    for (int i = ty; i < 32; i += 8)
        t[i][tx] = W[(size_t)(k0+i)*N + n0+tx];
    __syncthreads();
    for (int i = ty; i < 32; i += 8)
        outp[(size_t)(n0+i)*K + k0+tx] = __float2half_rn(t[tx][i]);
}

// ---------------- layernorm2: fp32 in -> fp16 out ----------------
__global__ void __launch_bounds__(128) ln_kernel(size_t Xoff, const float* __restrict__ gam,
                                                 const float* __restrict__ bet, size_t Yoff) {
    int row = blockIdx.x;
    const float* x = g_f + Xoff + (size_t)row*Cch;
    __half*      y = g_h + Yoff + (size_t)row*Cch;
    int c = threadIdx.x;
    float v0 = x[c], v1 = x[c+128], v2 = x[c+256];
    float s = v0+v1+v2, s2 = v0*v0 + v1*v1 + v2*v2;
    #pragma unroll
    for (int o = 16; o; o >>= 1) {
        s  += __shfl_xor_sync(0xffffffffu, s,  o);
        s2 += __shfl_xor_sync(0xffffffffu, s2, o);
    }
    __shared__ float rs[4], rs2[4];
    int wid = c >> 5;
    if ((c & 31) == 0) { rs[wid] = s; rs2[wid] = s2; }
    __syncthreads();
    s  = rs[0]+rs[1]+rs[2]+rs[3];
    s2 = rs2[0]+rs2[1]+rs2[2]+rs2[3];
    float mean = s * (1.0f/Cch);
    float var  = s2 * (1.0f/Cch) - mean*mean;
    float inv  = rsqrtf(var + 1e-5f);
    y[c]     = __float2half_rn((v0-mean)*inv*gam[c]     + bet[c]);
    y[c+128] = __float2half_rn((v1-mean)*inv*gam[c+128] + bet[c+128]);
    y[c+256] = __float2half_rn((v2-mean)*inv*gam[c+256] + bet[c+256]);
}

// ---------------- fp16 GEMM (round-12 verbatim): BK=16, LDS.64, 4-stage ------
#define EPI_BIAS_H 0
#define EPI_RES_F  1
#define EPI_GELU_H 2

#define HT_STG (128*16)
#define STAGES 4
constexpr int SMEM_HGEMM_BYTES = STAGES * 2 * HT_STG * 2;   // 32768

__global__ void __launch_bounds__(256, 2) hgemm_kernel(
    size_t Aoff, size_t Boff, const float* __restrict__ bias,
    long long resoff, size_t Coff, int N, int K, int epi)
{
    extern __shared__ __half smh[];
    __half* As = smh;
    __half* Bs = smh + STAGES*HT_STG;
    uint32_t as_sm = (uint32_t)__cvta_generic_to_shared(As);
    uint32_t bs_sm = (uint32_t)__cvta_generic_to_shared(Bs);

    int tid = threadIdx.x;
    int warp = tid >> 5, lane = tid & 31;
    int wrow = warp >> 2, wcol = warp & 3;
    int g = lane >> 2, qc = lane & 3;
    int brow = blockIdx.y, bcol = blockIdx.x;

    const __half* Ablk = g_h + Aoff + (size_t)brow*128*K;
    const __half* Bblk = g_h + Boff + (size_t)bcol*128*K;

    int lrow = tid >> 1;
    int lch  = (tid & 1) * 8;

    auto load_tile = [&](int s, int kt) {
        const __half* Ap = Ablk + (size_t)lrow*K + kt*16 + lch;
        const __half* Bp = Bblk + (size_t)lrow*K + kt*16 + lch;
        uint32_t off = (uint32_t)(s*HT_STG + lrow*16 + lch) * 2;
        cpa16(as_sm + off, Ap);
        cpa16(bs_sm + off, Bp);
    };

    float acc[4][4][4];
    #pragma unroll
    for (int i = 0; i < 4; i++)
        #pragma unroll
        for (int j = 0; j < 4; j++)
            #pragma unroll
            for (int r = 0; r < 4; r++) acc[i][j][r] = 0.f;

    int nk = K >> 4;
    load_tile(0, 0); cpa_commit();
    load_tile(1, 1); cpa_commit();
    load_tile(2, 2); cpa_commit();
    cpa_wait<2>();
    __syncthreads();

    int stage = 0;
    for (int kt = 0; kt < nk; kt++) {
        if (kt + 3 < nk) {
            int s = stage + 3 >= STAGES ? stage + 3 - STAGES : stage + 3;
            load_tile(s, kt + 3);
        }
        cpa_commit();

        const __half* Asb = As + stage*HT_STG;
        const __half* Bsb = Bs + stage*HT_STG;
        uint32_t af[4][4];
        #pragma unroll
        for (int i = 0; i < 4; i++) {
            int r = wrow*64 + i*16 + g;
            uint2 lo = *(const uint2*)(Asb + r*16     + 4*qc);
            uint2 hi = *(const uint2*)(Asb + (r+8)*16 + 4*qc);
            af[i][0] = lo.x; af[i][1] = hi.x; af[i][2] = lo.y; af[i][3] = hi.y;
        }
        uint32_t bf[4][2];
        #pragma unroll
        for (int j = 0; j < 4; j++) {
            int c = wcol*32 + j*8 + g;
            uint2 bb = *(const uint2*)(Bsb + c*16 + 4*qc);
            bf[j][0] = bb.x; bf[j][1] = bb.y;
        }
        #pragma unroll
        for (int i = 0; i < 4; i++)
            #pragma unroll
            for (int j = 0; j < 4; j++)
                mma_f16(acc[i][j], af[i], bf[j]);

        cpa_wait<2>();
        __syncthreads();
        stage = stage + 1 == STAGES ? 0 : stage + 1;
    }

    const float* res = (resoff >= 0) ? (g_f + (size_t)resoff) : nullptr;
    #pragma unroll
    for (int i = 0; i < 4; i++) {
        int r0 = brow*128 + wrow*64 + i*16 + g;
        #pragma unroll
        for (int j = 0; j < 4; j++) {
            int cb = bcol*128 + wcol*32 + j*8 + qc*2;
            float bx = bias[cb], by = bias[cb+1];
            #pragma unroll
            for (int half_ = 0; half_ < 2; half_++) {
                int row = r0 + half_*8;
                float vx = acc[i][j][half_*2]   + bx;
                float vy = acc[i][j][half_*2+1] + by;
                if (epi == EPI_RES_F) {
                    float2 rr = *(const float2*)(res + (size_t)row*N + cb);
                    vx += rr.x; vy += rr.y;
                    float2 o = {vx, vy};
                    *(float2*)(g_f + Coff + (size_t)row*N + cb) = o;
                } else {
                    if (epi == EPI_GELU_H) { vx = gelu_exact(vx); vy = gelu_exact(vy); }
                    *(__half2*)(g_h + Coff + (size_t)row*N + cb) =
                        __floats2half2_rn(vx, vy);
                }
            }
        }
    }
}

// ---------------- tensor-core attention, register-resident P (round-12) ------
__global__ void __launch_bounds__(128) attn_kernel(const float* __restrict__ rpb) {
    int blk = blockIdx.x;
    int h = blk % NHd;
    int w = blk / NHd;
    int ww = w & 7, wh = (w >> 3) & 7;
    int m0 = w * Ntok;

    __shared__ __half qh[64][40];
    __shared__ __half kh[56][40];
    __shared__ __half vT[32][72];
    __shared__ float  rpbh[169];
    __shared__ int    rid[Ntok];

    int tid = threadIdx.x;
    int warp = tid >> 5, lane = tid & 31;
    int g = lane >> 2, qc = lane & 3;

    for (int e = tid; e < 480; e += 128)
        vT[e / 15][49 + e % 15] = __float2half_rn(0.f);

    const __half* qkv = g_h + HOFF_QKV;
    if (tid < 98) {
        int i = tid >> 1, p = tid & 1;
        const __half* base = qkv + (size_t)(m0 + i)*(3*Cch) + h*HDim + p*16;
        *(uint4*)&qh[i][p*16]     = *(const uint4*)(base);
        *(uint4*)&qh[i][p*16 + 8] = *(const uint4*)(base + 8);
        *(uint4*)&kh[i][p*16]     = *(const uint4*)(base + Cch);
        *(uint4*)&kh[i][p*16 + 8] = *(const uint4*)(base + Cch + 8);
        const __half* vbase = base + 2*Cch;
        #pragma unroll
        for (int d = 0; d < 16; d++)
            vT[p*16 + d][i] = vbase[d];
    }
    for (int e = tid; e < 169; e += 128) rpbh[e] = rpb[e*NHd + h];
    if (tid < Ntok) {
        int r = tid / WS, c = tid % WS;
        rid[tid] = region(wh*WS + r)*3 + region(ww*WS + c);
    }
    __syncthreads();

    int r = warp*16 + g;
    int rlo = r, rhi = r + 8;
    bool lo_ok = rlo < Ntok, hi_ok = rhi < Ntok;
    int rid_lo = lo_ok ? rid[rlo] : 0;
    int rid_hi = hi_ok ? rid[rhi] : 0;
    int ri_lo = rlo / WS, ci_lo = rlo % WS;
    int ri_hi = rhi / WS, ci_hi = rhi % WS;

    float s[7][4];
    {
        uint32_t af[2][4];
        #pragma unroll
        for (int kc = 0; kc < 2; kc++) {
            af[kc][0] = *(const uint32_t*)&qh[rlo][kc*16 + 2*qc];
            af[kc][1] = *(const uint32_t*)&qh[rhi][kc*16 + 2*qc];
            af[kc][2] = *(const uint32_t*)&qh[rlo][kc*16 + 2*qc + 8];
            af[kc][3] = *(const uint32_t*)&qh[rhi][kc*16 + 2*qc + 8];
        }
        #pragma unroll
        for (int jt = 0; jt < 7; jt++) {
            float c4[4] = {0.f, 0.f, 0.f, 0.f};
            int col = jt*8 + g;
            uint32_t bf0[2], bf1[2];
            bf0[0] = *(const uint32_t*)&kh[col][2*qc];
            bf0[1] = *(const uint32_t*)&kh[col][2*qc + 8];
            bf1[0] = *(const uint32_t*)&kh[col][16 + 2*qc];
            bf1[1] = *(const uint32_t*)&kh[col][16 + 2*qc + 8];
            mma_f16(c4, af[0], bf0);
            mma_f16(c4, af[1], bf1);
            int c0 = jt*8 + 2*qc;
            #pragma unroll
            for (int u = 0; u < 4; u++) {
                int row_ok = (u & 2) ? hi_ok : lo_ok;
                int ccol = c0 + (u & 1);
                if (row_ok && ccol < Ntok) {
                    int ri = (u & 2) ? ri_hi : ri_lo;
                    int ci = (u & 2) ? ci_hi : ci_lo;
                    int rd = (u & 2) ? rid_hi : rid_lo;
                    int rj = ccol / WS, cj = ccol % WS;
                    float v = c4[u]*SCALE + rpbh[(ri - rj + 6)*13 + (ci - cj + 6)];
                    if (rd != rid[ccol]) v -= 100.f;
                    s[jt][u] = v;
                } else {
                    s[jt][u] = -1e30f;
                }
            }
        }
    }

    {
        float m_lo = -1e30f, m_hi = -1e30f;
        #pragma unroll
        for (int jt = 0; jt < 7; jt++) {
            m_lo = fmaxf(m_lo, fmaxf(s[jt][0], s[jt][1]));
            m_hi = fmaxf(m_hi, fmaxf(s[jt][2], s[jt][3]));
        }
        m_lo = fmaxf(m_lo, __shfl_xor_sync(0xffffffffu, m_lo, 1));
        m_lo = fmaxf(m_lo, __shfl_xor_sync(0xffffffffu, m_lo, 2));
        m_hi = fmaxf(m_hi, __shfl_xor_sync(0xffffffffu, m_hi, 1));
        m_hi = fmaxf(m_hi, __shfl_xor_sync(0xffffffffu, m_hi, 2));
        float sum_lo = 0.f, sum_hi = 0.f;
        #pragma unroll
        for (int jt = 0; jt < 7; jt++) {
            s[jt][0] = __expf(s[jt][0] - m_lo); sum_lo += s[jt][0];
            s[jt][1] = __expf(s[jt][1] - m_lo); sum_lo += s[jt][1];
            s[jt][2] = __expf(s[jt][2] - m_hi); sum_hi += s[jt][2];
            s[jt][3] = __expf(s[jt][3] - m_hi); sum_hi += s[jt][3];
        }
        sum_lo += __shfl_xor_sync(0xffffffffu, sum_lo, 1);
        sum_lo += __shfl_xor_sync(0xffffffffu, sum_lo, 2);
        sum_hi += __shfl_xor_sync(0xffffffffu, sum_hi, 1);
        sum_hi += __shfl_xor_sync(0xffffffffu, sum_hi, 2);
        float inv_lo = 1.0f / sum_lo, inv_hi = 1.0f / sum_hi;
        #pragma unroll
        for (int jt = 0; jt < 7; jt++) {
            s[jt][0] *= inv_lo; s[jt][1] *= inv_lo;
            s[jt][2] *= inv_hi; s[jt][3] *= inv_hi;
        }
    }

    uint32_t paf[4][4];
    #pragma unroll
    for (int kc = 0; kc < 3; kc++) {
        __half2 a0 = __floats2half2_rn(s[2*kc][0],   s[2*kc][1]);
        __half2 a1 = __floats2half2_rn(s[2*kc][2],   s[2*kc][3]);
        __half2 a2 = __floats2half2_rn(s[2*kc+1][0], s[2*kc+1][1]);
        __half2 a3 = __floats2half2_rn(s[2*kc+1][2], s[2*kc+1][3]);
        paf[kc][0] = *(uint32_t*)&a0; paf[kc][1] = *(uint32_t*)&a1;
        paf[kc][2] = *(uint32_t*)&a2; paf[kc][3] = *(uint32_t*)&a3;
    }
    {
        __half2 a0 = __floats2half2_rn(s[6][0], s[6][1]);
        __half2 a1 = __floats2half2_rn(s[6][2], s[6][3]);
        paf[3][0] = *(uint32_t*)&a0; paf[3][1] = *(uint32_t*)&a1;
        paf[3][2] = 0u; paf[3][3] = 0u;
    }

    __half* att = g_h + HOFF_ATT;
    #pragma unroll
    for (int ct = 0; ct < 4; ct++) {
        float c4[4] = {0.f, 0.f, 0.f, 0.f};
        int dcol = ct*8 + g;
        #pragma unroll
        for (int kc = 0; kc < 4; kc++) {
            uint32_t bf[2];
            bf[0] = *(const uint32_t*)&vT[dcol][kc*16 + 2*qc];
            bf[1] = *(const uint32_t*)&vT[dcol][kc*16 + 2*qc + 8];
            mma_f16(c4, paf[kc], bf);
        }
        int c0 = ct*8 + 2*qc;
        if (lo_ok)
            *(__half2*)(att + (size_t)(m0 + rlo)*Cch + h*HDim + c0) =
                __floats2half2_rn(c4[0], c4[1]);
        if (hi_ok)
            *(__half2*)(att + (size_t)(m0 + rhi)*Cch + h*HDim + c0) =
                __floats2half2_rn(c4[2], c4[3]);
    }
}

// ---------------- launch ----------------
extern "C" void kernel_launch(void* const* d_in, const int* in_sizes, int n_in,
                              void* d_out, int out_size) {
    const float* x      = (const float*)d_in[0];
    const float* qkv_w  = (const float*)d_in[1];
    const float* qkv_b  = (const float*)d_in[2];
    const float* proj_w = (const float*)d_in[3];
    const float* proj_b = (const float*)d_in[4];
    const float* rpb    = (const float*)d_in[5];
    const float* n1w    = (const float*)d_in[6];
    const float* n1b    = (const float*)d_in[7];
    const float* n2w    = (const float*)d_in[8];
    const float* n2b    = (const float*)d_in[9];
    const float* fc1w   = (const float*)d_in[10];
    const float* fc1b   = (const float*)d_in[11];
    const float* fc2w   = (const float*)d_in[12];
    const float* fc2b   = (const float*)d_in[13];
    float* out = (float*)d_out;

    cudaFuncSetAttribute(hgemm_kernel, cudaFuncAttributeMaxDynamicSharedMemorySize,
                         SMEM_HGEMM_BYTES);
    cudaFuncSetAttribute(tinln_kernel, cudaFuncAttributeMaxDynamicSharedMemorySize,
                         SMEM_TIN_BYTES);

    wtrans_all_kernel<<<1728, 256>>>(qkv_w, proj_w, fc1w, fc2w);

    tinln_kernel<<<dim3(56, 32), 256, SMEM_TIN_BYTES>>>(x, n1w, n1b);
    hgemm_kernel<<<dim3(1152/128, Mrows/128), 256, SMEM_HGEMM_BYTES>>>(
        HOFF_XLN, HOFF_WQKV, qkv_b, -1, HOFF_QKV, 1152, Cch, EPI_BIAS_H);
    attn_kernel<<<NWTOT * NHd, 128>>>(rpb);
    hgemm_kernel<<<dim3(384/128, Mrows/128), 256, SMEM_HGEMM_BYTES>>>(
        HOFF_ATT, HOFF_WPRJ, proj_b, (long long)OFF_XRAW, OFF_Y, Cch, Cch, EPI_RES_F);
    ln_kernel<<<Mrows, 128>>>(OFF_Y, n2w, n2b, HOFF_YLN);
    hgemm_kernel<<<dim3(1536/128, Mrows/128), 256, SMEM_HGEMM_BYTES>>>(
        HOFF_YLN, HOFF_WFC1, fc1b, -1, HOFF_H, HIDd, Cch, EPI_GELU_H);
    hgemm_kernel<<<dim3(384/128, Mrows/128), 256, SMEM_HGEMM_BYTES>>>(
        HOFF_H, HOFF_WFC2, fc2b, (long long)OFF_Y, OFF_FIN, Cch, HIDd, EPI_RES_F);
    tout_kernel<<<dim3(12, 56, 32), 256>>>(out);
}

// round 17
// speedup vs baseline: 1.0652x; 1.0100x over previous
#include <cuda_runtime.h>
#include <cuda_fp16.h>
#include <math.h>
#include <stdint.h>

// ---------------- problem constants ----------------
#define Bsz   32
#define Cch   384
#define Hh    56
#define Wwid  56
#define WS    7
#define SSH   3
#define NHd   12
#define Ntok  49
#define HDim  32
#define HIDd  1536
#define NWTOT 2048
#define Mrows (NWTOT*Ntok)         // 100352
#define SCALE 0.17677669529663687f

// ---------------- scratch ----------------
constexpr size_t OFF_XRAW = 0;                                  // [M,384] f32
constexpr size_t OFF_Y    = OFF_XRAW + (size_t)Mrows*Cch;       // [M,384] f32
constexpr size_t OFF_FIN  = OFF_Y    + (size_t)Mrows*Cch;       // [M,384] f32
constexpr size_t SCRATCH_F = OFF_FIN + (size_t)Mrows*Cch;

constexpr size_t HOFF_XLN  = 0;
constexpr size_t HOFF_QKV  = HOFF_XLN  + (size_t)Mrows*Cch;
constexpr size_t HOFF_ATT  = HOFF_QKV  + (size_t)Mrows*(3*Cch);
constexpr size_t HOFF_YLN  = HOFF_ATT  + (size_t)Mrows*Cch;
constexpr size_t HOFF_H    = HOFF_YLN  + (size_t)Mrows*Cch;
constexpr size_t HOFF_WQKV = HOFF_H    + (size_t)Mrows*HIDd;
constexpr size_t HOFF_WPRJ = HOFF_WQKV + (size_t)1152*384;
constexpr size_t HOFF_WFC1 = HOFF_WPRJ + (size_t)384*384;
constexpr size_t HOFF_WFC2 = HOFF_WFC1 + (size_t)1536*384;
constexpr size_t SCRATCH_H = HOFF_WFC2 + (size_t)384*1536;

__device__ __align__(16) float  g_f[SCRATCH_F];
__device__ __align__(16) __half g_h[SCRATCH_H];

// ---------------- helpers ----------------
__device__ __forceinline__ int region(int p) {
    return p < (Hh - WS) ? 0 : (p < (Hh - SSH) ? 1 : 2);
}
__device__ __forceinline__ float gelu_exact(float v) {
    return 0.5f * v * (1.0f + erff(v * 0.70710678118654752f));
}
__device__ __forceinline__ void mma_f16(float c[4], const uint32_t a[4], const uint32_t b[2]) {
    asm volatile(
        "mma.sync.aligned.m16n8k16.row.col.f32.f16.f16.f32 "
        "{%0,%1,%2,%3}, {%4,%5,%6,%7}, {%8,%9}, {%0,%1,%2,%3};\n"
        : "+f"(c[0]), "+f"(c[1]), "+f"(c[2]), "+f"(c[3])
        : "r"(a[0]), "r"(a[1]), "r"(a[2]), "r"(a[3]), "r"(b[0]), "r"(b[1]));
}
__device__ __forceinline__ void cpa16(uint32_t dst, const void* src) {
    asm volatile("cp.async.cg.shared.global [%0], [%1], 16;" :: "r"(dst), "l"(src));
}
__device__ __forceinline__ void cpa_commit() {
    asm volatile("cp.async.commit_group;" ::: "memory");
}
template <int N>
__device__ __forceinline__ void cpa_wait() {
    asm volatile("cp.async.wait_group %0;" :: "n"(N) : "memory");
}

// ---------------- fused transpose-in + LN1 ----------------
#define XS_STRIDE 57
constexpr int SMEM_TIN_BYTES = 384 * XS_STRIDE * 4;   // 87552

__global__ void __launch_bounds__(256) tinln_kernel(
    const float* __restrict__ x, const float* __restrict__ gam,
    const float* __restrict__ bet)
{
    extern __shared__ float xs[];
    int hh = blockIdx.x, b = blockIdx.y;
    int tid = threadIdx.x;
    int h0 = hh + SSH; if (h0 >= Hh) h0 -= Hh;

    const float* src = x + ((size_t)b*Cch)*(Hh*Wwid) + h0*Wwid;
    for (int e = tid; e < 384*56; e += 256) {
        int c = e / 56, ws = e - c*56;
        xs[c*XS_STRIDE + ws] = src[(size_t)c*(Hh*Wwid) + ws];
    }
    __syncthreads();

    int warp = tid >> 5, lane = tid & 31;
    int wh = hh / WS, r = hh % WS;

    float gm[12], bt[12];
    #pragma unroll
    for (int j = 0; j < 12; j++) { gm[j] = gam[lane + 32*j]; bt[j] = bet[lane + 32*j]; }

    for (int ts = warp*7; ts < warp*7 + 7; ts++) {
        int wsrc = ts + SSH; if (wsrc >= Wwid) wsrc -= Wwid;
        float v[12];
        float s = 0.f, s2 = 0.f;
        #pragma unroll
        for (int j = 0; j < 12; j++) {
            float t = xs[(lane + 32*j)*XS_STRIDE + wsrc];
            v[j] = t; s += t; s2 += t*t;
        }
        #pragma unroll
        for (int o = 16; o; o >>= 1) {
            s  += __shfl_xor_sync(0xffffffffu, s,  o);
            s2 += __shfl_xor_sync(0xffffffffu, s2, o);
        }
        float mean = s * (1.0f/Cch);
        float var  = s2 * (1.0f/Cch) - mean*mean;
        float inv  = rsqrtf(var + 1e-5f);

        int ww = ts / WS, cc = ts % WS;
        int m = (((b*8 + wh)*8 + ww)*Ntok) + r*WS + cc;
        float*  xr = g_f + OFF_XRAW + (size_t)m*Cch;
        __half* xl = g_h + HOFF_XLN + (size_t)m*Cch;
        #pragma unroll
        for (int j = 0; j < 12; j++) {
            int d = lane + 32*j;
            xr[d] = v[j];
            xl[d] = __float2half_rn((v[j]-mean)*inv*gm[j] + bt[j]);
        }
    }
}

// ---------------- transpose-out ----------------
__global__ void __launch_bounds__(256) tout_kernel(float* __restrict__ out) {
    int ct = blockIdx.x, h0 = blockIdx.y, b = blockIdx.z;
    __shared__ float tile[32][57];
    int hh = h0 - SSH; if (hh < 0) hh += Hh;
    int wh = hh / WS, r = hh % WS;
    for (int idx = threadIdx.x; idx < 56*32; idx += 256) {
        int t = idx >> 5, i = idx & 31;
        int ww = t / WS, c = t % WS;
        int m = (((b*8 + wh)*8 + ww)*Ntok) + r*WS + c;
        int w0 = t + SSH; if (w0 >= Wwid) w0 -= Wwid;
        tile[i][w0] = g_f[OFF_FIN + (size_t)m*Cch + ct*32 + i];
    }
    __syncthreads();
    for (int idx = threadIdx.x; idx < 32*56; idx += 256) {
        int i = idx / 56, w0 = idx - i*56;
        out[((size_t)(b*Cch + ct*32 + i))*(Hh*Wwid) + h0*Wwid + w0] = tile[i][w0];
    }
}

// ---------------- batched weight transpose ----------------
__global__ void __launch_bounds__(256) wtrans_all_kernel(
    const float* __restrict__ Wq, const float* __restrict__ Wp,
    const float* __restrict__ W1, const float* __restrict__ W2)
{
    __shared__ float t[32][33];
    int bidx = blockIdx.x;
    const float* W; int K, N, nb_n; size_t outoff;
    if (bidx < 432)      { W = Wq; K = Cch;  N = 1152; nb_n = 36; outoff = HOFF_WQKV; }
    else if (bidx < 576) { W = Wp; K = Cch;  N = 384;  nb_n = 12; outoff = HOFF_WPRJ; bidx -= 432; }
    else if (bidx < 1152){ W = W1; K = Cch;  N = 1536; nb_n = 48; outoff = HOFF_WFC1; bidx -= 576; }
    else                 { W = W2; K = HIDd; N = 384;  nb_n = 12; outoff = HOFF_WFC2; bidx -= 1152; }
    int n0 = (bidx % nb_n) * 32, k0 = (bidx / nb_n) * 32;

    int tx = threadIdx.x & 31, ty = threadIdx.x >> 5;
    __half* outp = g_h + outoff;
    for (int i = ty; i < 32; i += 8)
        t[i][tx] = W[(size_t)(k0+i)*N + n0+tx];
    __syncthreads();
    for (int i = ty; i < 32; i += 8)
        outp[(size_t)(n0+i)*K + k0+tx] = __float2half_rn(t[tx][i]);
}

// ---------------- layernorm2: fp32 in -> fp16 out ----------------
__global__ void __launch_bounds__(128) ln_kernel(size_t Xoff, const float* __restrict__ gam,
                                                 const float* __restrict__ bet, size_t Yoff) {
    int row = blockIdx.x;
    const float* x = g_f + Xoff + (size_t)row*Cch;
    __half*      y = g_h + Yoff + (size_t)row*Cch;
    int c = threadIdx.x;
    float v0 = x[c], v1 = x[c+128], v2 = x[c+256];
    float s = v0+v1+v2, s2 = v0*v0 + v1*v1 + v2*v2;
    #pragma unroll
    for (int o = 16; o; o >>= 1) {
        s  += __shfl_xor_sync(0xffffffffu, s,  o);
        s2 += __shfl_xor_sync(0xffffffffu, s2, o);
    }
    __shared__ float rs[4], rs2[4];
    int wid = c >> 5;
    if ((c & 31) == 0) { rs[wid] = s; rs2[wid] = s2; }
    __syncthreads();
    s  = rs[0]+rs[1]+rs[2]+rs[3];
    s2 = rs2[0]+rs2[1]+rs2[2]+rs2[3];
    float mean = s * (1.0f/Cch);
    float var  = s2 * (1.0f/Cch) - mean*mean;
    float inv  = rsqrtf(var + 1e-5f);
    y[c]     = __float2half_rn((v0-mean)*inv*gam[c]     + bet[c]);
    y[c+128] = __float2half_rn((v1-mean)*inv*gam[c+128] + bet[c+128]);
    y[c+256] = __float2half_rn((v2-mean)*inv*gam[c+256] + bet[c+256]);
}

// ---------------- fp16 GEMM (unchanged, 1917us baseline) ----------------
#define EPI_BIAS_H 0
#define EPI_RES_F  1
#define EPI_GELU_H 2

#define HT_STG (128*16)
#define STAGES 4
constexpr int SMEM_HGEMM_BYTES = STAGES * 2 * HT_STG * 2;   // 32768

__global__ void __launch_bounds__(256, 2) hgemm_kernel(
    size_t Aoff, size_t Boff, const float* __restrict__ bias,
    long long resoff, size_t Coff, int N, int K, int epi)
{
    extern __shared__ __half smh[];
    __half* As = smh;
    __half* Bs = smh + STAGES*HT_STG;
    uint32_t as_sm = (uint32_t)__cvta_generic_to_shared(As);
    uint32_t bs_sm = (uint32_t)__cvta_generic_to_shared(Bs);

    int tid = threadIdx.x;
    int warp = tid >> 5, lane = tid & 31;
    int wrow = warp >> 2, wcol = warp & 3;
    int g = lane >> 2, qc = lane & 3;
    int brow = blockIdx.y, bcol = blockIdx.x;

    const __half* Ablk = g_h + Aoff + (size_t)brow*128*K;
    const __half* Bblk = g_h + Boff + (size_t)bcol*128*K;

    int lrow = tid >> 1;
    int lch  = (tid & 1) * 8;

    auto load_tile = [&](int s, int kt) {
        const __half* Ap = Ablk + (size_t)lrow*K + kt*16 + lch;
        const __half* Bp = Bblk + (size_t)lrow*K + kt*16 + lch;
        uint32_t off = (uint32_t)(s*HT_STG + lrow*16 + lch) * 2;
        cpa16(as_sm + off, Ap);
        cpa16(bs_sm + off, Bp);
    };

    float acc[4][4][4];
    #pragma unroll
    for (int i = 0; i < 4; i++)
        #pragma unroll
        for (int j = 0; j < 4; j++)
            #pragma unroll
            for (int r = 0; r < 4; r++) acc[i][j][r] = 0.f;

    int nk = K >> 4;
    load_tile(0, 0); cpa_commit();
    load_tile(1, 1); cpa_commit();
    load_tile(2, 2); cpa_commit();
    cpa_wait<2>();
    __syncthreads();

    int stage = 0;
    for (int kt = 0; kt < nk; kt++) {
        if (kt + 3 < nk) {
            int s = stage + 3 >= STAGES ? stage + 3 - STAGES : stage + 3;
            load_tile(s, kt + 3);
        }
        cpa_commit();

        const __half* Asb = As + stage*HT_STG;
        const __half* Bsb = Bs + stage*HT_STG;
        uint32_t af[4][4];
        #pragma unroll
        for (int i = 0; i < 4; i++) {
            int r = wrow*64 + i*16 + g;
            uint2 lo = *(const uint2*)(Asb + r*16     + 4*qc);
            uint2 hi = *(const uint2*)(Asb + (r+8)*16 + 4*qc);
            af[i][0] = lo.x; af[i][1] = hi.x; af[i][2] = lo.y; af[i][3] = hi.y;
        }
        uint32_t bf[4][2];
        #pragma unroll
        for (int j = 0; j < 4; j++) {
            int c = wcol*32 + j*8 + g;
            uint2 bb = *(const uint2*)(Bsb + c*16 + 4*qc);
            bf[j][0] = bb.x; bf[j][1] = bb.y;
        }
        #pragma unroll
        for (int i = 0; i < 4; i++)
            #pragma unroll
            for (int j = 0; j < 4; j++)
                mma_f16(acc[i][j], af[i], bf[j]);

        cpa_wait<2>();
        __syncthreads();
        stage = stage + 1 == STAGES ? 0 : stage + 1;
    }

    const float* res = (resoff >= 0) ? (g_f + (size_t)resoff) : nullptr;
    #pragma unroll
    for (int i = 0; i < 4; i++) {
        int r0 = brow*128 + wrow*64 + i*16 + g;
        #pragma unroll
        for (int j = 0; j < 4; j++) {
            int cb = bcol*128 + wcol*32 + j*8 + qc*2;
            float bx = bias[cb], by = bias[cb+1];
            #pragma unroll
            for (int half_ = 0; half_ < 2; half_++) {
                int row = r0 + half_*8;
                float vx = acc[i][j][half_*2]   + bx;
                float vy = acc[i][j][half_*2+1] + by;
                if (epi == EPI_RES_F) {
                    float2 rr = *(const float2*)(res + (size_t)row*N + cb);
                    vx += rr.x; vy += rr.y;
                    float2 o = {vx, vy};
                    *(float2*)(g_f + Coff + (size_t)row*N + cb) = o;
                } else {
                    if (epi == EPI_GELU_H) { vx = gelu_exact(vx); vy = gelu_exact(vy); }
                    *(__half2*)(g_h + Coff + (size_t)row*N + cb) =
                        __floats2half2_rn(vx, vy);
                }
            }
        }
    }
}

// ---------------- tensor-core attention, packed-position bias index ----------
// rpi = (ri-rj+6)*13 + (ci-cj+6) == qpos[i] - qpos[j] + 84, qpos[t]=(t/7)*13+t%7.
// pk[t] = qpos[t] | (rid[t]<<16); pad tokens rid=0xFFFF (-100 mask always fires).
// Pad rows of qh (49..63) and kh (49..55) are ZEROED so pad MMA results are
// finite 0, making the -100 mask numerically equivalent to the old -1e30 path.
__global__ void __launch_bounds__(128) attn_kernel(const float* __restrict__ rpb) {
    int blk = blockIdx.x;
    int h = blk % NHd;
    int w = blk / NHd;
    int ww = w & 7, wh = (w >> 3) & 7;
    int m0 = w * Ntok;

    __shared__ __half qh[64][40];
    __shared__ __half kh[56][40];
    __shared__ __half vT[32][72];
    __shared__ float  rpbh[169];
    __shared__ int    pk[64];

    int tid = threadIdx.x;
    int warp = tid >> 5, lane = tid & 31;
    int g = lane >> 2, qc = lane & 3;

    // zero vT pad columns (tokens 49..63)
    for (int e = tid; e < 480; e += 128)
        vT[e / 15][49 + e % 15] = __float2half_rn(0.f);
    // zero qh pad rows 49..63 (15 rows x 40h = 600) — 32-bit stores
    for (int e = tid; e < 300; e += 128)
        ((uint32_t*)&qh[49][0])[e] = 0u;
    // zero kh pad rows 49..55 (7 rows x 40h = 280) — 32-bit stores
    for (int e = tid; e < 140; e += 128)
        ((uint32_t*)&kh[49][0])[e] = 0u;

    const __half* qkv = g_h + HOFF_QKV;
    if (tid < 98) {
        int i = tid >> 1, p = tid & 1;
        const __half* base = qkv + (size_t)(m0 + i)*(3*Cch) + h*HDim + p*16;
        *(uint4*)&qh[i][p*16]     = *(const uint4*)(base);
        *(uint4*)&qh[i][p*16 + 8] = *(const uint4*)(base + 8);
        *(uint4*)&kh[i][p*16]     = *(const uint4*)(base + Cch);
        *(uint4*)&kh[i][p*16 + 8] = *(const uint4*)(base + Cch + 8);
        const __half* vbase = base + 2*Cch;
        #pragma unroll
        for (int d = 0; d < 16; d++)
            vT[p*16 + d][i] = vbase[d];
    }
    for (int e = tid; e < 169; e += 128) rpbh[e] = rpb[e*NHd + h];
    if (tid < 64) {
        if (tid < Ntok) {
            int r = tid / WS, c = tid % WS;
            int rid = region(wh*WS + r)*3 + region(ww*WS + c);
            pk[tid] = (r*13 + c) | (rid << 16);
        } else {
            pk[tid] = 0 | (0xFFFF << 16);   // pad: mask always fires
        }
    }
    __syncthreads();

    int r = warp*16 + g;
    int rlo = r, rhi = r + 8;
    bool lo_ok = rlo < Ntok, hi_ok = rhi < Ntok;
    int pk_lo = pk[rlo], pk_hi = pk[rhi];
    int base_lo = (pk_lo & 0xFFFF) + 84, rid_lo = pk_lo >> 16;
    int base_hi = (pk_hi & 0xFFFF) + 84, rid_hi = pk_hi >> 16;

    // ---- QK^T into registers s[7][4] ----
    float s[7][4];
    {
        uint32_t af[2][4];
        #pragma unroll
        for (int kc = 0; kc < 2; kc++) {
            af[kc][0] = *(const uint32_t*)&qh[rlo][kc*16 + 2*qc];
            af[kc][1] = *(const uint32_t*)&qh[rhi][kc*16 + 2*qc];
            af[kc][2] = *(const uint32_t*)&qh[rlo][kc*16 + 2*qc + 8];
            af[kc][3] = *(const uint32_t*)&qh[rhi][kc*16 + 2*qc + 8];
        }
        #pragma unroll
        for (int jt = 0; jt < 7; jt++) {
            float c4[4] = {0.f, 0.f, 0.f, 0.f};
            int col = jt*8 + g;
            uint32_t bf0[2], bf1[2];
            bf0[0] = *(const uint32_t*)&kh[col][2*qc];
            bf0[1] = *(const uint32_t*)&kh[col][2*qc + 8];
            bf1[0] = *(const uint32_t*)&kh[col][16 + 2*qc];
            bf1[1] = *(const uint32_t*)&kh[col][16 + 2*qc + 8];
            mma_f16(c4, af[0], bf0);
            mma_f16(c4, af[1], bf1);
            int c0 = jt*8 + 2*qc;
            int pj0 = pk[c0], pj1 = pk[c0 + 1];
            float v0 = c4[0]*SCALE + rpbh[base_lo - (pj0 & 0xFFFF)];
            float v1 = c4[1]*SCALE + rpbh[base_lo - (pj1 & 0xFFFF)];
            float v2 = c4[2]*SCALE + rpbh[base_hi - (pj0 & 0xFFFF)];
            float v3 = c4[3]*SCALE + rpbh[base_hi - (pj1 & 0xFFFF)];
            if (rid_lo != (pj0 >> 16)) v0 -= 100.f;
            if (rid_lo != (pj1 >> 16)) v1 -= 100.f;
            if (rid_hi != (pj0 >> 16)) v2 -= 100.f;
            if (rid_hi != (pj1 >> 16)) v3 -= 100.f;
            s[jt][0] = v0; s[jt][1] = v1; s[jt][2] = v2; s[jt][3] = v3;
        }
    }

    // ---- softmax in registers (quad shfl over qc) ----
    {
        float m_lo = -1e30f, m_hi = -1e30f;
        #pragma unroll
        for (int jt = 0; jt < 7; jt++) {
            m_lo = fmaxf(m_lo, fmaxf(s[jt][0], s[jt][1]));
            m_hi = fmaxf(m_hi, fmaxf(s[jt][2], s[jt][3]));
        }
        m_lo = fmaxf(m_lo, __shfl_xor_sync(0xffffffffu, m_lo, 1));
        m_lo = fmaxf(m_lo, __shfl_xor_sync(0xffffffffu, m_lo, 2));
        m_hi = fmaxf(m_hi, __shfl_xor_sync(0xffffffffu, m_hi, 1));
        m_hi = fmaxf(m_hi, __shfl_xor_sync(0xffffffffu, m_hi, 2));
        float sum_lo = 0.f, sum_hi = 0.f;
        #pragma unroll
        for (int jt = 0; jt < 7; jt++) {
            s[jt][0] = __expf(s[jt][0] - m_lo); sum_lo += s[jt][0];
            s[jt][1] = __expf(s[jt][1] - m_lo); sum_lo += s[jt][1];
            s[jt][2] = __expf(s[jt][2] - m_hi); sum_hi += s[jt][2];
            s[jt][3] = __expf(s[jt][3] - m_hi); sum_hi += s[jt][3];
        }
        sum_lo += __shfl_xor_sync(0xffffffffu, sum_lo, 1);
        sum_lo += __shfl_xor_sync(0xffffffffu, sum_lo, 2);
        sum_hi += __shfl_xor_sync(0xffffffffu, sum_hi, 1);
        sum_hi += __shfl_xor_sync(0xffffffffu, sum_hi, 2);
        float inv_lo = 1.0f / sum_lo, inv_hi = 1.0f / sum_hi;
        #pragma unroll
        for (int jt = 0; jt < 7; jt++) {
            s[jt][0] *= inv_lo; s[jt][1] *= inv_lo;
            s[jt][2] *= inv_hi; s[jt][3] *= inv_hi;
        }
    }

    // ---- build P.V A-fragments directly from registers ----
    uint32_t paf[4][4];
    #pragma unroll
    for (int kc = 0; kc < 3; kc++) {
        __half2 a0 = __floats2half2_rn(s[2*kc][0],   s[2*kc][1]);
        __half2 a1 = __floats2half2_rn(s[2*kc][2],   s[2*kc][3]);
        __half2 a2 = __floats2half2_rn(s[2*kc+1][0], s[2*kc+1][1]);
        __half2 a3 = __floats2half2_rn(s[2*kc+1][2], s[2*kc+1][3]);
        paf[kc][0] = *(uint32_t*)&a0; paf[kc][1] = *(uint32_t*)&a1;
        paf[kc][2] = *(uint32_t*)&a2; paf[kc][3] = *(uint32_t*)&a3;
    }
    {
        __half2 a0 = __floats2half2_rn(s[6][0], s[6][1]);
        __half2 a1 = __floats2half2_rn(s[6][2], s[6][3]);
        paf[3][0] = *(uint32_t*)&a0; paf[3][1] = *(uint32_t*)&a1;
        paf[3][2] = 0u; paf[3][3] = 0u;
    }

    // ---- P.V ----
    __half* att = g_h + HOFF_ATT;
    #pragma unroll
    for (int ct = 0; ct < 4; ct++) {
        float c4[4] = {0.f, 0.f, 0.f, 0.f};
        int dcol = ct*8 + g;
        #pragma unroll
        for (int kc = 0; kc < 4; kc++) {
            uint32_t bf[2];
            bf[0] = *(const uint32_t*)&vT[dcol][kc*16 + 2*qc];
            bf[1] = *(const uint32_t*)&vT[dcol][kc*16 + 2*qc + 8];
            mma_f16(c4, paf[kc], bf);
        }
        int c0 = ct*8 + 2*qc;
        if (lo_ok)
            *(__half2*)(att + (size_t)(m0 + rlo)*Cch + h*HDim + c0) =
                __floats2half2_rn(c4[0], c4[1]);
        if (hi_ok)
            *(__half2*)(att + (size_t)(m0 + rhi)*Cch + h*HDim + c0) =
                __floats2half2_rn(c4[2], c4[3]);
    }
}

// ---------------- launch ----------------
extern "C" void kernel_launch(void* const* d_in, const int* in_sizes, int n_in,
                              void* d_out, int out_size) {
    const float* x      = (const float*)d_in[0];
    const float* qkv_w  = (const float*)d_in[1];
    const float* qkv_b  = (const float*)d_in[2];
    const float* proj_w = (const float*)d_in[3];
    const float* proj_b = (const float*)d_in[4];
    const float* rpb    = (const float*)d_in[5];
    const float* n1w    = (const float*)d_in[6];
    const float* n1b    = (const float*)d_in[7];
    const float* n2w    = (const float*)d_in[8];
    const float* n2b    = (const float*)d_in[9];
    const float* fc1w   = (const float*)d_in[10];
    const float* fc1b   = (const float*)d_in[11];
    const float* fc2w   = (const float*)d_in[12];
    const float* fc2b   = (const float*)d_in[13];
    float* out = (float*)d_out;

    cudaFuncSetAttribute(hgemm_kernel, cudaFuncAttributeMaxDynamicSharedMemorySize,
                         SMEM_HGEMM_BYTES);
    cudaFuncSetAttribute(tinln_kernel, cudaFuncAttributeMaxDynamicSharedMemorySize,
                         SMEM_TIN_BYTES);

    wtrans_all_kernel<<<1728, 256>>>(qkv_w, proj_w, fc1w, fc2w);

    tinln_kernel<<<dim3(56, 32), 256, SMEM_TIN_BYTES>>>(x, n1w, n1b);
    hgemm_kernel<<<dim3(1152/128, Mrows/128), 256, SMEM_HGEMM_BYTES>>>(
        HOFF_XLN, HOFF_WQKV, qkv_b, -1, HOFF_QKV, 1152, Cch, EPI_BIAS_H);
    attn_kernel<<<NWTOT * NHd, 128>>>(rpb);
    hgemm_kernel<<<dim3(384/128, Mrows/128), 256, SMEM_HGEMM_BYTES>>>(
        HOFF_ATT, HOFF_WPRJ, proj_b, (long long)OFF_XRAW, OFF_Y, Cch, Cch, EPI_RES_F);
    ln_kernel<<<Mrows, 128>>>(OFF_Y, n2w, n2b, HOFF_YLN);
    hgemm_kernel<<<dim3(1536/128, Mrows/128), 256, SMEM_HGEMM_BYTES>>>(
        HOFF_YLN, HOFF_WFC1, fc1b, -1, HOFF_H, HIDd, Cch, EPI_GELU_H);
    hgemm_kernel<<<dim3(384/128, Mrows/128), 256, SMEM_HGEMM_BYTES>>>(
        HOFF_H, HOFF_WFC2, fc2b, (long long)OFF_Y, OFF_FIN, Cch, HIDd, EPI_RES_F);
    tout_kernel<<<dim3(12, 56, 32), 256>>>(out);
}